// round 1
// baseline (speedup 1.0000x reference)
#include <cuda_runtime.h>

#define S_   512
#define H_   16
#define D_   24
#define DS_  384
#define CZ_  128
#define EPS_ 1e-5f
#define SCALE_ 0.20412414523193152f   // 24^-0.5

// -------- scratch (no allocations allowed) --------
__device__ float g_q[S_*DS_];
__device__ float g_k[S_*DS_];
__device__ float g_v[S_*DS_];
__device__ float g_g[S_*DS_];
__device__ float g_o[S_*DS_];
__device__ float g_bias[H_*S_*S_];     // [H][S][S], includes seq_mask

// ============================================================
// GEMM C[M,N] = A[M,K] * W[N,K]^T   (64x64 tiles, 4x4 microtile)
// ============================================================
__global__ __launch_bounds__(256) void gemm_qkvg_kernel(
    const float* __restrict__ s,
    const float* __restrict__ qw, const float* __restrict__ qb,
    const float* __restrict__ kw, const float* __restrict__ vw,
    const float* __restrict__ gw)
{
    __shared__ float As[32][68];
    __shared__ float Bs[32][68];
    const int var = blockIdx.z;
    const float* W = (var==0)?qw:(var==1)?kw:(var==2)?vw:gw;
    float* C = (var==0)?g_q:(var==1)?g_k:(var==2)?g_v:g_g;
    const int m0 = blockIdx.y*64, n0 = blockIdx.x*64;
    const int tid = threadIdx.x;
    const int tx = tid & 15, ty = tid >> 4;
    const int lk = tid & 31, lr = tid >> 5;
    float acc[4][4] = {};

    for (int k0 = 0; k0 < DS_; k0 += 32) {
        #pragma unroll
        for (int r = 0; r < 8; r++) {
            As[lk][lr + 8*r] = s[(m0 + lr + 8*r)*DS_ + k0 + lk];
            Bs[lk][lr + 8*r] = W[(n0 + lr + 8*r)*DS_ + k0 + lk];
        }
        __syncthreads();
        #pragma unroll
        for (int kk = 0; kk < 32; kk++) {
            float4 a = *(const float4*)&As[kk][ty*4];
            float4 b = *(const float4*)&Bs[kk][tx*4];
            float av[4] = {a.x,a.y,a.z,a.w};
            float bv[4] = {b.x,b.y,b.z,b.w};
            #pragma unroll
            for (int i = 0; i < 4; i++)
                #pragma unroll
                for (int j = 0; j < 4; j++)
                    acc[i][j] += av[i]*bv[j];
        }
        __syncthreads();
    }

    const int col = n0 + tx*4;
    #pragma unroll
    for (int i = 0; i < 4; i++) {
        float4 r;
        r.x = acc[i][0]; r.y = acc[i][1]; r.z = acc[i][2]; r.w = acc[i][3];
        if (var == 0) { r.x += qb[col]; r.y += qb[col+1]; r.z += qb[col+2]; r.w += qb[col+3]; }
        if (var == 3) {
            r.x = 1.f/(1.f+__expf(-r.x));
            r.y = 1.f/(1.f+__expf(-r.y));
            r.z = 1.f/(1.f+__expf(-r.z));
            r.w = 1.f/(1.f+__expf(-r.w));
        }
        *(float4*)&C[(m0 + ty*4 + i)*DS_ + col] = r;
    }
}

// output GEMM: A = g_o * g_g (elementwise), W = o_w, C = out
__global__ __launch_bounds__(256) void gemm_out_kernel(
    const float* __restrict__ W, float* __restrict__ C)
{
    __shared__ float As[32][68];
    __shared__ float Bs[32][68];
    const int m0 = blockIdx.y*64, n0 = blockIdx.x*64;
    const int tid = threadIdx.x;
    const int tx = tid & 15, ty = tid >> 4;
    const int lk = tid & 31, lr = tid >> 5;
    float acc[4][4] = {};

    for (int k0 = 0; k0 < DS_; k0 += 32) {
        #pragma unroll
        for (int r = 0; r < 8; r++) {
            int ai = (m0 + lr + 8*r)*DS_ + k0 + lk;
            As[lk][lr + 8*r] = g_o[ai] * g_g[ai];
            Bs[lk][lr + 8*r] = W[(n0 + lr + 8*r)*DS_ + k0 + lk];
        }
        __syncthreads();
        #pragma unroll
        for (int kk = 0; kk < 32; kk++) {
            float4 a = *(const float4*)&As[kk][ty*4];
            float4 b = *(const float4*)&Bs[kk][tx*4];
            float av[4] = {a.x,a.y,a.z,a.w};
            float bv[4] = {b.x,b.y,b.z,b.w};
            #pragma unroll
            for (int i = 0; i < 4; i++)
                #pragma unroll
                for (int j = 0; j < 4; j++)
                    acc[i][j] += av[i]*bv[j];
        }
        __syncthreads();
    }

    const int col = n0 + tx*4;
    #pragma unroll
    for (int i = 0; i < 4; i++) {
        float4 r;
        r.x = acc[i][0]; r.y = acc[i][1]; r.z = acc[i][2]; r.w = acc[i][3];
        *(float4*)&C[(m0 + ty*4 + i)*DS_ + col] = r;
    }
}

// ============================================================
// bias = LN(z) @ z_w^T + seq_mask   -> g_bias[H][S][S]
// warp per z-row (128 chans). z_w held in registers (64/lane).
// multi-value butterfly reduction: 16 partials -> 1 per lane pair.
// ============================================================
#define FOLD_STEP(n, msk) { \
    const bool bit_ = (lane & (msk)) != 0; \
    _Pragma("unroll") \
    for (int ii = 0; ii < (n)/2; ii++) { \
        float lo_ = p[ii], hi_ = p[ii + (n)/2]; \
        float sv_ = bit_ ? lo_ : hi_; \
        float rv_ = __shfl_xor_sync(0xffffffffu, sv_, (msk)); \
        p[ii] = bit_ ? (hi_ + rv_) : (lo_ + rv_); \
    } }

__global__ __launch_bounds__(256) void bias_kernel(
    const float* __restrict__ z, const float* __restrict__ mask,
    const float* __restrict__ lnw, const float* __restrict__ lnb,
    const float* __restrict__ zw)
{
    const int lane = threadIdx.x & 31;
    const int gwarp = (blockIdx.x * 256 + threadIdx.x) >> 5;
    const int nwarp = (gridDim.x * 256) >> 5;

    const float4 w4 = *(const float4*)&lnw[lane*4];
    const float4 b4 = *(const float4*)&lnb[lane*4];
    float4 zr[16];
    #pragma unroll
    for (int hh = 0; hh < 16; hh++) zr[hh] = *(const float4*)&zw[hh*CZ_ + lane*4];

    for (int row = gwarp; row < S_*S_; row += nwarp) {
        float4 x = *(const float4*)&z[(size_t)row*CZ_ + lane*4];
        float sum = x.x + x.y + x.z + x.w;
        float ssq = x.x*x.x + x.y*x.y + x.z*x.z + x.w*x.w;
        #pragma unroll
        for (int m = 16; m >= 1; m >>= 1) {
            sum += __shfl_xor_sync(0xffffffffu, sum, m);
            ssq += __shfl_xor_sync(0xffffffffu, ssq, m);
        }
        const float mu   = sum * (1.f/CZ_);
        const float var  = ssq * (1.f/CZ_) - mu*mu;
        const float rinv = rsqrtf(var + EPS_);
        const float y0 = (x.x-mu)*rinv*w4.x + b4.x;
        const float y1 = (x.y-mu)*rinv*w4.y + b4.y;
        const float y2 = (x.z-mu)*rinv*w4.z + b4.z;
        const float y3 = (x.w-mu)*rinv*w4.w + b4.w;

        float p[16];
        #pragma unroll
        for (int hh = 0; hh < 16; hh++)
            p[hh] = y0*zr[hh].x + y1*zr[hh].y + y2*zr[hh].z + y3*zr[hh].w;

        FOLD_STEP(16, 16)
        FOLD_STEP(8, 8)
        FOLD_STEP(4, 4)
        FOLD_STEP(2, 2)
        p[0] += __shfl_xor_sync(0xffffffffu, p[0], 1);

        if (!(lane & 1)) {
            const int hh = lane >> 1;                // head index
            const int i = row >> 9, j = row & 511;
            g_bias[(hh*S_ + i)*S_ + j] = p[0] + mask[j];
        }
    }
}

// ============================================================
// attention: block = (head h, 32 q-rows). K/V/scores in smem.
// ============================================================
extern __shared__ float smem_attn[];
__global__ __launch_bounds__(256, 1) void attn_kernel()
{
    float* ks = smem_attn;               // [512][25]
    float* vs = smem_attn + 512*25;      // [512][25]
    float* sc = smem_attn + 2*512*25;    // [32][513]
    const int h   = blockIdx.y;
    const int qi0 = blockIdx.x * 32;
    const int tid = threadIdx.x;
    const int lane = tid & 31;

    // K,V tiles for this head -> smem (padded rows, conflict-free)
    for (int idx = tid; idx < S_*D_; idx += 256) {
        int i = idx / D_, d = idx - i*D_;
        ks[i*25 + d] = g_k[i*DS_ + h*D_ + d];
        vs[i*25 + d] = g_v[i*DS_ + h*D_ + d];
    }

    // each thread owns 4 q rows (group by warp) held in registers
    const int qib = (tid >> 5) * 4;
    float qr[4][24];
    #pragma unroll
    for (int i = 0; i < 4; i++)
        #pragma unroll
        for (int d = 0; d < 24; d++)
            qr[i][d] = g_q[(qi0 + qib + i)*DS_ + h*D_ + d];
    __syncthreads();

    // scores = q.k^T * scale + bias
    const float* bias_row = &g_bias[(h*S_ + qi0 + qib)*S_];
    #pragma unroll 1
    for (int u = 0; u < 16; u++) {
        const int kj = lane + 32*u;
        float kr[24];
        #pragma unroll
        for (int d = 0; d < 24; d++) kr[d] = ks[kj*25 + d];
        #pragma unroll
        for (int i = 0; i < 4; i++) {
            float acc = 0.f;
            #pragma unroll
            for (int d = 0; d < 24; d++) acc += qr[i][d]*kr[d];
            sc[(qib + i)*513 + kj] = acc*SCALE_ + bias_row[i*S_ + kj];
        }
    }
    __syncthreads();

    // softmax: each warp does 4 rows
    {
        const int w = tid >> 5;
        for (int rr = 0; rr < 4; rr++) {
            float* p = &sc[(w*4 + rr)*513];
            float mx = -1e30f;
            #pragma unroll
            for (int t = 0; t < 16; t++) mx = fmaxf(mx, p[lane + 32*t]);
            #pragma unroll
            for (int m = 16; m >= 1; m >>= 1) mx = fmaxf(mx, __shfl_xor_sync(0xffffffffu, mx, m));
            float e[16];
            float sum = 0.f;
            #pragma unroll
            for (int t = 0; t < 16; t++) { e[t] = __expf(p[lane + 32*t] - mx); sum += e[t]; }
            #pragma unroll
            for (int m = 16; m >= 1; m >>= 1) sum += __shfl_xor_sync(0xffffffffu, sum, m);
            const float rinv = 1.f / sum;
            #pragma unroll
            for (int t = 0; t < 16; t++) p[lane + 32*t] = e[t]*rinv;
        }
    }
    __syncthreads();

    // O = P @ V : thread owns (qi = tid&31, 3 consecutive d)
    {
        const int qi = tid & 31;
        const int db = (tid >> 5) * 3;
        float a0 = 0.f, a1 = 0.f, a2 = 0.f;
        const float* p = &sc[qi*513];
        #pragma unroll 4
        for (int kj = 0; kj < S_; kj++) {
            const float pv = p[kj];
            a0 += pv * vs[kj*25 + db + 0];
            a1 += pv * vs[kj*25 + db + 1];
            a2 += pv * vs[kj*25 + db + 2];
        }
        float* op = &g_o[(qi0 + qi)*DS_ + h*D_ + db];
        op[0] = a0; op[1] = a1; op[2] = a2;
    }
}

// ============================================================
extern "C" void kernel_launch(void* const* d_in, const int* in_sizes, int n_in,
                              void* d_out, int out_size)
{
    const float* s   = (const float*)d_in[0];
    const float* z   = (const float*)d_in[1];
    const float* msk = (const float*)d_in[2];
    const float* qw  = (const float*)d_in[3];
    const float* qb  = (const float*)d_in[4];
    const float* kw  = (const float*)d_in[5];
    const float* vw  = (const float*)d_in[6];
    const float* gw  = (const float*)d_in[7];
    const float* ow  = (const float*)d_in[8];
    const float* lnw = (const float*)d_in[9];
    const float* lnb = (const float*)d_in[10];
    const float* zw  = (const float*)d_in[11];
    float* out = (float*)d_out;

    const int smem = (2*512*25 + 32*513) * 4;   // 168064 B
    cudaFuncSetAttribute(attn_kernel, cudaFuncAttributeMaxDynamicSharedMemorySize, smem);

    gemm_qkvg_kernel<<<dim3(6, 8, 4), 256>>>(s, qw, qb, kw, vw, gw);
    bias_kernel<<<2048, 256>>>(z, msk, lnw, lnb, zw);
    attn_kernel<<<dim3(16, 16), 256, smem>>>();
    gemm_out_kernel<<<dim3(6, 8), 256>>>(ow, out);
}

// round 2
// speedup vs baseline: 1.0136x; 1.0136x over previous
#include <cuda_runtime.h>

#define S_   512
#define H_   16
#define D_   24
#define DS_  384
#define CZ_  128
#define EPS_ 1e-5f
#define SCALE_ 0.20412414523193152f   // 24^-0.5

#define NG_     384                   // gemm blocks in fused kernel (96 per variant)
#define NB_     2048                  // bias blocks in fused kernel
#define NTILES_ 8192                  // (512*512)/32 rows per tile

// -------- scratch (no allocations allowed) --------
__device__ float g_qt[H_*S_*D_];      // [H][S][D], q pre-scaled by D^-0.5
__device__ float g_kt[H_*S_*D_];
__device__ float g_vt[H_*S_*D_];
__device__ float g_g[S_*DS_];
__device__ float g_o[S_*DS_];
__device__ float g_bias[H_*S_*S_];    // includes seq_mask

// ============================================================
// multi-value butterfly fold (verified round 1)
// ============================================================
#define FOLD_STEP(n, msk) { \
    const bool bit_ = (lane & (msk)) != 0; \
    _Pragma("unroll") \
    for (int ii = 0; ii < (n)/2; ii++) { \
        float lo_ = p[ii], hi_ = p[ii + (n)/2]; \
        float sv_ = bit_ ? lo_ : hi_; \
        float rv_ = __shfl_xor_sync(0xffffffffu, sv_, (msk)); \
        p[ii] = bit_ ? (hi_ + rv_) : (lo_ + rv_); \
    } }

// ============================================================
// Fused kernel: blocks [0,NG_) do the 4 QKVG GEMMs (32x64 tiles),
// blocks [NG_, NG_+NB_) do LN(z)@z_w^T + mask -> g_bias.
// Mixing memory-bound bias blocks with FMA-bound GEMM blocks on the
// same SMs hides both latencies.
// ============================================================
__global__ __launch_bounds__(256, 2) void fused_qkvg_bias_kernel(
    const float* __restrict__ s,
    const float* __restrict__ qw, const float* __restrict__ qb,
    const float* __restrict__ kw, const float* __restrict__ vw,
    const float* __restrict__ gw,
    const float* __restrict__ z, const float* __restrict__ mask,
    const float* __restrict__ lnw, const float* __restrict__ lnb,
    const float* __restrict__ zw)
{
    const int tid = threadIdx.x;
    const int lane = tid & 31;

    if (blockIdx.x < NG_) {
        // ---------------- GEMM path: C[M,N] = A[M,K] * W[N,K]^T ----------------
        __shared__ float As[32][34];   // [k][m] (pad keeps float2 8B-aligned)
        __shared__ float Bs[32][68];   // [k][n]
        const int b   = blockIdx.x;
        const int var = b / 96;
        const int r   = b % 96;
        const int n0  = (r % 6) * 64;
        const int m0  = (r / 6) * 32;
        const float* W = (var==0)?qw:(var==1)?kw:(var==2)?vw:gw;
        const int tx = tid & 15, ty = tid >> 4;
        const int lk = tid & 31, lm = tid >> 5;
        float acc[2][4] = {};

        for (int k0 = 0; k0 < DS_; k0 += 32) {
            #pragma unroll
            for (int i = 0; i < 4; i++)
                As[lk][lm + 8*i] = s[(m0 + lm + 8*i)*DS_ + k0 + lk];
            #pragma unroll
            for (int i = 0; i < 8; i++)
                Bs[lk][lm + 8*i] = W[(n0 + lm + 8*i)*DS_ + k0 + lk];
            __syncthreads();
            #pragma unroll
            for (int kk = 0; kk < 32; kk++) {
                const float2 a = *(const float2*)&As[kk][ty*2];
                const float4 bv = *(const float4*)&Bs[kk][tx*4];
                acc[0][0] += a.x*bv.x; acc[0][1] += a.x*bv.y; acc[0][2] += a.x*bv.z; acc[0][3] += a.x*bv.w;
                acc[1][0] += a.y*bv.x; acc[1][1] += a.y*bv.y; acc[1][2] += a.y*bv.z; acc[1][3] += a.y*bv.w;
            }
            __syncthreads();
        }

        const int col = n0 + tx*4;
        #pragma unroll
        for (int i = 0; i < 2; i++) {
            const int row = m0 + ty*2 + i;
            float4 rv = make_float4(acc[i][0], acc[i][1], acc[i][2], acc[i][3]);
            if (var == 0) {
                rv.x += qb[col]; rv.y += qb[col+1]; rv.z += qb[col+2]; rv.w += qb[col+3];
            }
            if (var == 3) {
                rv.x = 1.f/(1.f+__expf(-rv.x));
                rv.y = 1.f/(1.f+__expf(-rv.y));
                rv.z = 1.f/(1.f+__expf(-rv.z));
                rv.w = 1.f/(1.f+__expf(-rv.w));
                *(float4*)&g_g[row*DS_ + col] = rv;
            } else {
                // transposed head-major store; q pre-scaled
                const int hh = col / D_;
                const int dd = col - hh*D_;
                if (var == 0) { rv.x *= SCALE_; rv.y *= SCALE_; rv.z *= SCALE_; rv.w *= SCALE_; }
                float* dst = (var==0) ? g_qt : (var==1) ? g_kt : g_vt;
                *(float4*)&dst[(hh*S_ + row)*D_ + dd] = rv;
            }
        }
    } else {
        // ---------------- bias path: warp per z-row ----------------
        __shared__ float smb[16][34];   // [head][j within 32-tile] (pad for float2)
        const int w = tid >> 5;
        const float4 w4 = *(const float4*)&lnw[lane*4];
        const float4 b4 = *(const float4*)&lnb[lane*4];
        float4 zr[16];
        #pragma unroll
        for (int hh = 0; hh < 16; hh++) zr[hh] = *(const float4*)&zw[hh*CZ_ + lane*4];

        const int bb = blockIdx.x - NG_;
        for (int t = bb; t < NTILES_; t += NB_) {
            const int r0 = t * 32;            // 32 consecutive rows: same i, j0..j0+31
            const int i  = r0 >> 9;
            const int j0 = r0 & 511;

            #pragma unroll 1
            for (int rr = 0; rr < 4; rr++) {
                const int jj  = w*4 + rr;
                const int row = r0 + jj;
                float4 x = *(const float4*)&z[(size_t)row*CZ_ + lane*4];
                float sum = x.x + x.y + x.z + x.w;
                float ssq = x.x*x.x + x.y*x.y + x.z*x.z + x.w*x.w;
                #pragma unroll
                for (int m = 16; m >= 1; m >>= 1) {
                    sum += __shfl_xor_sync(0xffffffffu, sum, m);
                    ssq += __shfl_xor_sync(0xffffffffu, ssq, m);
                }
                const float mu   = sum * (1.f/CZ_);
                const float var_ = ssq * (1.f/CZ_) - mu*mu;
                const float rinv = rsqrtf(var_ + EPS_);
                const float y0 = (x.x-mu)*rinv*w4.x + b4.x;
                const float y1 = (x.y-mu)*rinv*w4.y + b4.y;
                const float y2 = (x.z-mu)*rinv*w4.z + b4.z;
                const float y3 = (x.w-mu)*rinv*w4.w + b4.w;

                float p[16];
                #pragma unroll
                for (int hh = 0; hh < 16; hh++)
                    p[hh] = y0*zr[hh].x + y1*zr[hh].y + y2*zr[hh].z + y3*zr[hh].w;

                FOLD_STEP(16, 16)
                FOLD_STEP(8, 8)
                FOLD_STEP(4, 4)
                FOLD_STEP(2, 2)
                p[0] += __shfl_xor_sync(0xffffffffu, p[0], 1);

                if (!(lane & 1)) smb[lane >> 1][jj] = p[0];
            }
            __syncthreads();
            {   // coalesced write-out: 16 threads per head, float2 each
                const int hh = tid >> 4;
                const int j2 = (tid & 15) * 2;
                float2 o;
                o.x = smb[hh][j2]     + mask[j0 + j2];
                o.y = smb[hh][j2 + 1] + mask[j0 + j2 + 1];
                *(float2*)&g_bias[(hh*S_ + i)*S_ + j0 + j2] = o;
            }
            __syncthreads();
        }
    }
}

// ============================================================
// attention: block = (head, 32 q-rows). Scores-only smem (65.7KB,
// 2 blocks/SM). K/V read straight from L2 (head-major, coalesced).
// ============================================================
extern __shared__ float smem_attn[];
__global__ __launch_bounds__(256, 2) void attn_kernel()
{
    float* sc = smem_attn;               // [32][513]
    const int h    = blockIdx.y;
    const int qi0  = blockIdx.x * 32;
    const int tid  = threadIdx.x;
    const int lane = tid & 31;
    const int w    = tid >> 5;
    const int qib  = w * 4;

    // q rows (pre-scaled) in registers, replicated per lane
    float qr[4][24];
    #pragma unroll
    for (int i = 0; i < 4; i++) {
        const float4* qp = (const float4*)&g_qt[(h*S_ + qi0 + qib + i)*D_];
        #pragma unroll
        for (int c = 0; c < 6; c++) {
            float4 v = qp[c];
            qr[i][c*4+0] = v.x; qr[i][c*4+1] = v.y; qr[i][c*4+2] = v.z; qr[i][c*4+3] = v.w;
        }
    }

    // scores = q.k^T + bias
    const float* bias_row = &g_bias[(h*S_ + qi0 + qib)*S_];
    #pragma unroll 1
    for (int u = 0; u < 16; u++) {
        const int kj = lane + 32*u;
        const float4* kp = (const float4*)&g_kt[(h*S_ + kj)*D_];
        float a0 = 0.f, a1 = 0.f, a2 = 0.f, a3 = 0.f;
        #pragma unroll
        for (int c = 0; c < 6; c++) {
            const float4 kv = kp[c];
            a0 += qr[0][c*4]*kv.x + qr[0][c*4+1]*kv.y + qr[0][c*4+2]*kv.z + qr[0][c*4+3]*kv.w;
            a1 += qr[1][c*4]*kv.x + qr[1][c*4+1]*kv.y + qr[1][c*4+2]*kv.z + qr[1][c*4+3]*kv.w;
            a2 += qr[2][c*4]*kv.x + qr[2][c*4+1]*kv.y + qr[2][c*4+2]*kv.z + qr[2][c*4+3]*kv.w;
            a3 += qr[3][c*4]*kv.x + qr[3][c*4+1]*kv.y + qr[3][c*4+2]*kv.z + qr[3][c*4+3]*kv.w;
        }
        sc[(qib+0)*513 + kj] = a0 + bias_row[0*S_ + kj];
        sc[(qib+1)*513 + kj] = a1 + bias_row[1*S_ + kj];
        sc[(qib+2)*513 + kj] = a2 + bias_row[2*S_ + kj];
        sc[(qib+3)*513 + kj] = a3 + bias_row[3*S_ + kj];
    }
    __syncthreads();

    // softmax: warp does its own 4 rows
    #pragma unroll 1
    for (int rr = 0; rr < 4; rr++) {
        float* p = &sc[(qib + rr)*513];
        float mx = -1e30f;
        #pragma unroll
        for (int t = 0; t < 16; t++) mx = fmaxf(mx, p[lane + 32*t]);
        #pragma unroll
        for (int m = 16; m >= 1; m >>= 1) mx = fmaxf(mx, __shfl_xor_sync(0xffffffffu, mx, m));
        float e[16];
        float sum = 0.f;
        #pragma unroll
        for (int t = 0; t < 16; t++) { e[t] = __expf(p[lane + 32*t] - mx); sum += e[t]; }
        #pragma unroll
        for (int m = 16; m >= 1; m >>= 1) sum += __shfl_xor_sync(0xffffffffu, sum, m);
        const float rinv = 1.f / sum;
        #pragma unroll
        for (int t = 0; t < 16; t++) p[lane + 32*t] = e[t]*rinv;
    }
    __syncthreads();

    // O = P @ V : thread owns (qi = lane, 3 consecutive d = warp*3)
    {
        const int qi = lane;
        const int db = w * 3;
        float a0 = 0.f, a1 = 0.f, a2 = 0.f;
        const float* p = &sc[qi*513];
        const float* vb = &g_vt[h*S_*D_ + db];
        #pragma unroll 8
        for (int kj = 0; kj < S_; kj++) {
            const float pv = p[kj];
            a0 += pv * vb[kj*D_ + 0];
            a1 += pv * vb[kj*D_ + 1];
            a2 += pv * vb[kj*D_ + 2];
        }
        float* op = &g_o[(qi0 + qi)*DS_ + h*D_ + db];
        op[0] = a0; op[1] = a1; op[2] = a2;
    }
}

// ============================================================
// out = (o * g) @ o_w^T  : 16x64 tiles -> 192 blocks
// ============================================================
__global__ __launch_bounds__(256) void gemm_out_kernel(
    const float* __restrict__ W, float* __restrict__ C)
{
    __shared__ float As[32][17];   // [k][m]
    __shared__ float Bs[32][68];   // [k][n]
    const int n0 = blockIdx.x*64, m0 = blockIdx.y*16;
    const int tid = threadIdx.x;
    const int tx = tid & 15, ty = tid >> 4;
    const int lk = tid & 31, lm = tid >> 5;
    float acc[4] = {};

    for (int k0 = 0; k0 < DS_; k0 += 32) {
        #pragma unroll
        for (int i = 0; i < 2; i++) {
            const int m = lm + 8*i;
            const int ai = (m0 + m)*DS_ + k0 + lk;
            As[lk][m] = g_o[ai] * g_g[ai];
        }
        #pragma unroll
        for (int i = 0; i < 8; i++)
            Bs[lk][lm + 8*i] = W[(n0 + lm + 8*i)*DS_ + k0 + lk];
        __syncthreads();
        #pragma unroll
        for (int kk = 0; kk < 32; kk++) {
            const float a = As[kk][ty];
            const float4 b = *(const float4*)&Bs[kk][tx*4];
            acc[0] += a*b.x; acc[1] += a*b.y; acc[2] += a*b.z; acc[3] += a*b.w;
        }
        __syncthreads();
    }
    *(float4*)&C[(m0 + ty)*DS_ + n0 + tx*4] = make_float4(acc[0], acc[1], acc[2], acc[3]);
}

// ============================================================
extern "C" void kernel_launch(void* const* d_in, const int* in_sizes, int n_in,
                              void* d_out, int out_size)
{
    const float* s   = (const float*)d_in[0];
    const float* z   = (const float*)d_in[1];
    const float* msk = (const float*)d_in[2];
    const float* qw  = (const float*)d_in[3];
    const float* qb  = (const float*)d_in[4];
    const float* kw  = (const float*)d_in[5];
    const float* vw  = (const float*)d_in[6];
    const float* gw  = (const float*)d_in[7];
    const float* ow  = (const float*)d_in[8];
    const float* lnw = (const float*)d_in[9];
    const float* lnb = (const float*)d_in[10];
    const float* zw  = (const float*)d_in[11];
    float* out = (float*)d_out;

    const int smem = 32*513*4;   // 65664 B
    cudaFuncSetAttribute(attn_kernel, cudaFuncAttributeMaxDynamicSharedMemorySize, smem);

    fused_qkvg_bias_kernel<<<NG_ + NB_, 256>>>(s, qw, qb, kw, vw, gw,
                                               z, msk, lnw, lnb, zw);
    attn_kernel<<<dim3(16, 16), 256, smem>>>();
    gemm_out_kernel<<<dim3(6, 32), 256>>>(ow, out);
}